// round 1
// baseline (speedup 1.0000x reference)
#include <cuda_runtime.h>

#define NN 200000
#define NE 400000
#define HS 128

// ---------------- scratch (device globals; no allocs allowed) ----------------
__device__ float g_xf[NN * HS];          // x @ w_f^T + b_f               [N,128]
__device__ float g_hsum[NN * HS];        // segment_sum(h_child[src])     [N,128]
__device__ float g_fcsum[NN * HS];       // segment_sum(f * c_child[src]) [N,128]
__device__ float g_iou[NN * 3 * HS];     // pre-activation i|o|u          [N,384]
__device__ float g_wfT[HS * HS];         // w_f transposed  [K=128][N=128]
__device__ float g_ufT[HS * HS];         // u_f transposed  [K=128][N=128]
__device__ float g_bcat[2 * HS * 3 * HS];// [w_iou^T ; u_iou^T]  [K=256][N=384]

__device__ __forceinline__ float sigmoidf(float v) {
    return 1.0f / (1.0f + __expf(-v));
}

// ---------------- zero the accumulators ----------------
__global__ void k_zero() {
    int i = blockIdx.x * blockDim.x + threadIdx.x;
    const int total4 = NN * HS / 4;
    if (i < total4) {
        float4 z = make_float4(0.f, 0.f, 0.f, 0.f);
        reinterpret_cast<float4*>(g_hsum)[i] = z;
        reinterpret_cast<float4*>(g_fcsum)[i] = z;
    }
}

// ---------------- transpose weights into GEMM-friendly layouts ----------------
__global__ void k_prep(const float* __restrict__ w_iou, const float* __restrict__ u_iou,
                       const float* __restrict__ w_f,   const float* __restrict__ u_f) {
    int i = blockIdx.x * blockDim.x + threadIdx.x;
    if (i < 256 * 384) {
        int k = i / 384, n = i % 384;
        g_bcat[i] = (k < 128) ? w_iou[n * 128 + k] : u_iou[n * 128 + (k - 128)];
        return;
    }
    int j = i - 256 * 384;
    if (j < 128 * 128) {
        int k = j / 128, n = j % 128;
        g_wfT[j] = w_f[n * 128 + k];
        g_ufT[j] = u_f[n * 128 + k];
    }
}

// ---------------- hsum scatter: one warp per edge, float4 reads, scalar atomics ----------------
__global__ void k_scatter_h(const float* __restrict__ h_child,
                            const int* __restrict__ esrc, const int* __restrict__ edst) {
    int idx = blockIdx.x * blockDim.x + threadIdx.x;
    int e = idx >> 5;
    int q = idx & 31;
    if (e >= NE) return;
    int s = esrc[e];
    int d = edst[e];
    float4 v = reinterpret_cast<const float4*>(h_child + (size_t)s * HS)[q];
    float* dst = g_hsum + (size_t)d * HS + q * 4;
    atomicAdd(dst + 0, v.x);
    atomicAdd(dst + 1, v.y);
    atomicAdd(dst + 2, v.z);
    atomicAdd(dst + 3, v.w);
}

// ============================================================================
// Tiled SGEMM core: 128x128 block tile, K-step 16, 8x8 per thread, 256 threads.
// Warp-swizzled thread map: warp covers 32 rows x 64 cols -> A reads broadcast,
// B reads 2-way. As padded to 132 for conflict-free transposed stores.
// ============================================================================

// GEMM1: g_xf[N,128] = x[N,128] @ g_wfT + b_f
__global__ void __launch_bounds__(256) k_gemm_xf(const float* __restrict__ x,
                                                 const float* __restrict__ b_f) {
    __shared__ float As[16][132];
    __shared__ float Bs[16][128];
    const int tid  = threadIdx.x;
    const int lane = tid & 31, w = tid >> 5;
    const int tr = (w & 3) * 4 + (lane >> 3);   // 0..15 row-thread
    const int tc = (w >> 2) * 8 + (lane & 7);   // 0..15 col-thread
    const int brow = blockIdx.x * 128;
    const int aRow = tid >> 2;
    const int aC   = (tid & 3) * 4;

    float acc[8][8];
#pragma unroll
    for (int i = 0; i < 8; i++)
#pragma unroll
        for (int j = 0; j < 8; j++) acc[i][j] = 0.f;

    for (int kt = 0; kt < 128; kt += 16) {
#pragma unroll
        for (int ii = 0; ii < 2; ii++) {
            int m = aRow + ii * 64;
            int r = brow + m;
            float4 v = make_float4(0.f, 0.f, 0.f, 0.f);
            if (r < NN) v = *reinterpret_cast<const float4*>(x + (size_t)r * HS + kt + aC);
            As[aC + 0][m] = v.x; As[aC + 1][m] = v.y;
            As[aC + 2][m] = v.z; As[aC + 3][m] = v.w;
        }
#pragma unroll
        for (int ii = 0; ii < 2; ii++) {
            int f  = tid + ii * 256;
            int bR = f >> 5, bC = (f & 31) * 4;
            *reinterpret_cast<float4*>(&Bs[bR][bC]) =
                *reinterpret_cast<const float4*>(&g_wfT[(kt + bR) * HS + bC]);
        }
        __syncthreads();
#pragma unroll
        for (int k = 0; k < 16; k++) {
            float a[8], b[8];
#pragma unroll
            for (int i = 0; i < 8; i++) a[i] = As[k][tr * 8 + i];
#pragma unroll
            for (int j = 0; j < 8; j++) b[j] = Bs[k][tc * 8 + j];
#pragma unroll
            for (int i = 0; i < 8; i++)
#pragma unroll
                for (int j = 0; j < 8; j++) acc[i][j] += a[i] * b[j];
        }
        __syncthreads();
    }
#pragma unroll
    for (int i = 0; i < 8; i++) {
        int r = brow + tr * 8 + i;
        if (r >= NN) continue;
#pragma unroll
        for (int j = 0; j < 8; j++) {
            int col = tc * 8 + j;
            g_xf[(size_t)r * HS + col] = acc[i][j] + b_f[col];
        }
    }
}

// GEMM2 (edges): Z[E,128] = h_child[esrc] @ g_ufT, fused epilogue:
//   f = sigmoid(g_xf[dst] + Z); atomicAdd(g_fcsum[dst], f * c_child[src])
__global__ void __launch_bounds__(256) k_gemm_edge(const float* __restrict__ h_child,
                                                   const float* __restrict__ c_child,
                                                   const int* __restrict__ esrc,
                                                   const int* __restrict__ edst) {
    __shared__ float As[16][132];
    __shared__ float Bs[16][128];
    __shared__ int s_src[128];
    __shared__ int s_dst[128];
    const int tid  = threadIdx.x;
    const int lane = tid & 31, w = tid >> 5;
    const int tr = (w & 3) * 4 + (lane >> 3);
    const int tc = (w >> 2) * 8 + (lane & 7);
    const int brow = blockIdx.x * 128;
    const int aRow = tid >> 2;
    const int aC   = (tid & 3) * 4;

    if (tid < 128) {
        int e = brow + tid;
        s_src[tid] = (e < NE) ? esrc[e] : 0;
        s_dst[tid] = (e < NE) ? edst[e] : 0;
    }
    __syncthreads();

    const int src0 = s_src[aRow];
    const int src1 = s_src[aRow + 64];
    const float* arow0 = h_child + (size_t)src0 * HS;
    const float* arow1 = h_child + (size_t)src1 * HS;

    float acc[8][8];
#pragma unroll
    for (int i = 0; i < 8; i++)
#pragma unroll
        for (int j = 0; j < 8; j++) acc[i][j] = 0.f;

    for (int kt = 0; kt < 128; kt += 16) {
        {
            float4 v0 = *reinterpret_cast<const float4*>(arow0 + kt + aC);
            float4 v1 = *reinterpret_cast<const float4*>(arow1 + kt + aC);
            As[aC + 0][aRow] = v0.x; As[aC + 1][aRow] = v0.y;
            As[aC + 2][aRow] = v0.z; As[aC + 3][aRow] = v0.w;
            As[aC + 0][aRow + 64] = v1.x; As[aC + 1][aRow + 64] = v1.y;
            As[aC + 2][aRow + 64] = v1.z; As[aC + 3][aRow + 64] = v1.w;
        }
#pragma unroll
        for (int ii = 0; ii < 2; ii++) {
            int f  = tid + ii * 256;
            int bR = f >> 5, bC = (f & 31) * 4;
            *reinterpret_cast<float4*>(&Bs[bR][bC]) =
                *reinterpret_cast<const float4*>(&g_ufT[(kt + bR) * HS + bC]);
        }
        __syncthreads();
#pragma unroll
        for (int k = 0; k < 16; k++) {
            float a[8], b[8];
#pragma unroll
            for (int i = 0; i < 8; i++) a[i] = As[k][tr * 8 + i];
#pragma unroll
            for (int j = 0; j < 8; j++) b[j] = Bs[k][tc * 8 + j];
#pragma unroll
            for (int i = 0; i < 8; i++)
#pragma unroll
                for (int j = 0; j < 8; j++) acc[i][j] += a[i] * b[j];
        }
        __syncthreads();
    }

#pragma unroll
    for (int i = 0; i < 8; i++) {
        int m = tr * 8 + i;
        int e = brow + m;
        if (e >= NE) continue;
        int s = s_src[m];
        int d = s_dst[m];
        const float* crow = c_child + (size_t)s * HS;
        const float* xfr  = g_xf + (size_t)d * HS;
        float* fcr        = g_fcsum + (size_t)d * HS;
#pragma unroll
        for (int j = 0; j < 8; j++) {
            int col = tc * 8 + j;
            float f  = sigmoidf(acc[i][j] + xfr[col]);
            atomicAdd(&fcr[col], f * crow[col]);
        }
    }
}

// GEMM3: g_iou[N,384] = [x | g_hsum][N,256] @ g_bcat[256,384] + b_iou
__global__ void __launch_bounds__(256) k_gemm_iou(const float* __restrict__ x,
                                                  const float* __restrict__ b_iou) {
    __shared__ float As[16][132];
    __shared__ float Bs[16][128];
    const int tid  = threadIdx.x;
    const int lane = tid & 31, w = tid >> 5;
    const int tr = (w & 3) * 4 + (lane >> 3);
    const int tc = (w >> 2) * 8 + (lane & 7);
    const int brow = blockIdx.x * 128;
    const int bcol = blockIdx.y * 128;
    const int aRow = tid >> 2;
    const int aC   = (tid & 3) * 4;

    float acc[8][8];
#pragma unroll
    for (int i = 0; i < 8; i++)
#pragma unroll
        for (int j = 0; j < 8; j++) acc[i][j] = 0.f;

    for (int kt = 0; kt < 256; kt += 16) {
        const float* Asrc = (kt < 128) ? x : g_hsum;
        const int ko = (kt < 128) ? kt : (kt - 128);
#pragma unroll
        for (int ii = 0; ii < 2; ii++) {
            int m = aRow + ii * 64;
            int r = brow + m;
            float4 v = make_float4(0.f, 0.f, 0.f, 0.f);
            if (r < NN) v = *reinterpret_cast<const float4*>(Asrc + (size_t)r * HS + ko + aC);
            As[aC + 0][m] = v.x; As[aC + 1][m] = v.y;
            As[aC + 2][m] = v.z; As[aC + 3][m] = v.w;
        }
#pragma unroll
        for (int ii = 0; ii < 2; ii++) {
            int f  = tid + ii * 256;
            int bR = f >> 5, bC = (f & 31) * 4;
            *reinterpret_cast<float4*>(&Bs[bR][bC]) =
                *reinterpret_cast<const float4*>(&g_bcat[(kt + bR) * 384 + bcol + bC]);
        }
        __syncthreads();
#pragma unroll
        for (int k = 0; k < 16; k++) {
            float a[8], b[8];
#pragma unroll
            for (int i = 0; i < 8; i++) a[i] = As[k][tr * 8 + i];
#pragma unroll
            for (int j = 0; j < 8; j++) b[j] = Bs[k][tc * 8 + j];
#pragma unroll
            for (int i = 0; i < 8; i++)
#pragma unroll
                for (int j = 0; j < 8; j++) acc[i][j] += a[i] * b[j];
        }
        __syncthreads();
    }
#pragma unroll
    for (int i = 0; i < 8; i++) {
        int r = brow + tr * 8 + i;
        if (r >= NN) continue;
#pragma unroll
        for (int j = 0; j < 8; j++) {
            int col = bcol + tc * 8 + j;
            g_iou[(size_t)r * 384 + col] = acc[i][j] + b_iou[col];
        }
    }
}

// ---------------- final node update: h = o*tanh(c), c = i*u + fc_sum ----------------
__global__ void k_final(float* __restrict__ out) {
    int idx = blockIdx.x * blockDim.x + threadIdx.x;
    if (idx >= NN * HS) return;
    int n = idx >> 7;
    int j = idx & 127;
    size_t b = (size_t)n * 384;
    float iv = g_iou[b + j];
    float ov = g_iou[b + 128 + j];
    float uv = g_iou[b + 256 + j];
    float i_ = sigmoidf(iv);
    float o_ = sigmoidf(ov);
    float u_ = tanhf(uv);
    float c  = i_ * u_ + g_fcsum[idx];
    float h  = o_ * tanhf(c);
    out[idx] = h;
    out[(size_t)NN * HS + idx] = c;
}

// ============================================================================
extern "C" void kernel_launch(void* const* d_in, const int* in_sizes, int n_in,
                              void* d_out, int out_size) {
    const float* x       = (const float*)d_in[0];
    const float* h_child = (const float*)d_in[1];
    const float* c_child = (const float*)d_in[2];
    const float* w_iou   = (const float*)d_in[3];
    const float* b_iou   = (const float*)d_in[4];
    const float* w_f     = (const float*)d_in[5];
    const float* b_f     = (const float*)d_in[6];
    const float* u_iou   = (const float*)d_in[7];
    const float* u_f     = (const float*)d_in[8];
    const int*   esrc    = (const int*)d_in[9];
    const int*   edst    = (const int*)d_in[10];
    float* out = (float*)d_out;

    k_zero<<<(NN * HS / 4 + 255) / 256, 256>>>();
    k_prep<<<(256 * 384 + 128 * 128 + 255) / 256, 256>>>(w_iou, u_iou, w_f, u_f);
    k_gemm_xf<<<(NN + 127) / 128, 256>>>(x, b_f);
    k_scatter_h<<<(NE * 32 + 255) / 256, 256>>>(h_child, esrc, edst);
    k_gemm_edge<<<NE / 128, 256>>>(h_child, c_child, esrc, edst);
    dim3 g3((NN + 127) / 128, 3);
    k_gemm_iou<<<g3, 256>>>(x, b_iou);
    k_final<<<(NN * HS + 255) / 256, 256>>>(out);
}

// round 3
// speedup vs baseline: 1.4540x; 1.4540x over previous
#include <cuda_runtime.h>
#include <cuda_bf16.h>
#include <cstdint>

#define NN 200000
#define NE 400000
#define HS 128
#define ROW_TILES 1563   // ceil(200000/128)

#define LDA 136                // padded row stride (elems) for smem tiles
#define ASZ (128 * LDA)        // elems per smem tile buffer
#define SMEM_BYTES (4 * ASZ * 2)

// ---------------- scratch (device globals; no allocs allowed) ----------------
__device__ float g_xall[(size_t)NN * 512];   // x@[w_iou;w_f]^T + bias  [N,512] = i|o|u|xf
__device__ float g_hu[(size_t)NN * HS];      // h_child @ u_f^T         [N,128]
__device__ float g_hsum[(size_t)NN * HS];    // segsum(h_child[src])    [N,128]
__device__ float g_fcsum[(size_t)NN * HS];   // segsum(f*c_child[src])  [N,128]
__device__ float g_uhsum[(size_t)NN * 384];  // hsum @ u_iou^T          [N,384]
// packed bf16 weights, 8 tiles of [128 n][128 k] row-major:
// tiles 0-3: [w_iou;w_f] (512 rows), 4-6: u_iou (384), 7: u_f (128)
__device__ __nv_bfloat16 g_Bhi[8 * 16384];
__device__ __nv_bfloat16 g_Blo[8 * 16384];
__device__ float g_bias[512];

__device__ __forceinline__ float sigmoidf(float v) { return 1.0f / (1.0f + __expf(-v)); }

__device__ __forceinline__ uint32_t smem_u32(const void* p) {
    uint32_t a;
    asm("{ .reg .u64 t; cvta.to.shared.u64 t, %1; cvt.u32.u64 %0, t; }" : "=r"(a) : "l"(p));
    return a;
}

__device__ __forceinline__ void ldsm4(uint32_t* r, uint32_t addr) {
    asm volatile("ldmatrix.sync.aligned.m8n8.x4.shared.b16 {%0,%1,%2,%3}, [%4];"
                 : "=r"(r[0]), "=r"(r[1]), "=r"(r[2]), "=r"(r[3]) : "r"(addr));
}

__device__ __forceinline__ void mma16816(float* c, const uint32_t* a, uint32_t b0, uint32_t b1) {
    asm volatile(
        "mma.sync.aligned.m16n8k16.row.col.f32.bf16.bf16.f32 "
        "{%0,%1,%2,%3}, {%4,%5,%6,%7}, {%8,%9}, {%0,%1,%2,%3};"
        : "+f"(c[0]), "+f"(c[1]), "+f"(c[2]), "+f"(c[3])
        : "r"(a[0]), "r"(a[1]), "r"(a[2]), "r"(a[3]), "r"(b0), "r"(b1));
}

__device__ __forceinline__ uint32_t pack2(__nv_bfloat16 lo, __nv_bfloat16 hi) {
    return (uint32_t)__bfloat16_as_ushort(lo) | ((uint32_t)__bfloat16_as_ushort(hi) << 16);
}

// ---------------- zero the accumulators ----------------
__global__ void k_zero() {
    int i = blockIdx.x * blockDim.x + threadIdx.x;
    const int total4 = NN * HS / 4;
    if (i < total4) {
        float4 z = make_float4(0.f, 0.f, 0.f, 0.f);
        reinterpret_cast<float4*>(g_hsum)[i] = z;
        reinterpret_cast<float4*>(g_fcsum)[i] = z;
    }
}

// ---------------- pack weights: fp32 -> bf16 hi/lo, row-major [n][k] tiles ----------------
__global__ void k_prep(const float* __restrict__ w_iou, const float* __restrict__ w_f,
                       const float* __restrict__ u_iou, const float* __restrict__ u_f,
                       const float* __restrict__ b_iou, const float* __restrict__ b_f) {
    int i = blockIdx.x * blockDim.x + threadIdx.x;
    if (i < 512) g_bias[i] = (i < 384) ? b_iou[i] : b_f[i - 384];
    if (i >= 131072) return;
    int n, k, tile;
    float val;
    if (i < 65536) {                       // [w_iou ; w_f], 512 rows
        n = i >> 7; k = i & 127;
        tile = n >> 7;
        val = (n < 384) ? w_iou[n * 128 + k] : w_f[(n - 384) * 128 + k];
    } else if (i < 65536 + 49152) {        // u_iou, 384 rows
        int j = i - 65536;
        n = j >> 7; k = j & 127;
        tile = 4 + (n >> 7);
        val = u_iou[n * 128 + k];
    } else {                               // u_f, 128 rows
        int j = i - 114688;
        n = j >> 7; k = j & 127;
        tile = 7;
        val = u_f[n * 128 + k];
    }
    __nv_bfloat16 hi = __float2bfloat16(val);
    __nv_bfloat16 lo = __float2bfloat16(val - __bfloat162float(hi));
    int off = tile * 16384 + (n & 127) * 128 + k;
    g_Bhi[off] = hi;
    g_Blo[off] = lo;
}

// ============================================================================
// bf16 mma.sync GEMM: D[128,128] fp32 = A[128,128]fp32 @ B^T (B = [n][k])
// 3-term split: Ahi*Bhi + Ahi*Blo + Alo*Bhi.
// sel 0: A=x       -> g_xall  (stride 512, +bias, btiles 0..3)
// sel 1: A=h_child -> g_hu    (stride 128, btile 7)
// sel 2: A=g_hsum  -> g_uhsum (stride 384, btiles 4..6)
// ============================================================================
__global__ void __launch_bounds__(256) k_mma(const float* __restrict__ xin,
                                             const float* __restrict__ hin,
                                             int sel) {
    const float* A   = (sel == 0) ? xin : (sel == 1) ? hin : g_hsum;
    float*       out = (sel == 0) ? g_xall : (sel == 1) ? g_hu : g_uhsum;
    const int ostride = (sel == 0) ? 512 : (sel == 1) ? 128 : 384;
    const int btile   = ((sel == 0) ? 0 : (sel == 1) ? 7 : 4) + blockIdx.y;
    const bool usebias = (sel == 0);

    extern __shared__ __nv_bfloat16 sm[];
    __nv_bfloat16* sAhi = sm;
    __nv_bfloat16* sAlo = sm + ASZ;
    __nv_bfloat16* sBhi = sm + 2 * ASZ;
    __nv_bfloat16* sBlo = sm + 3 * ASZ;

    const int tid = threadIdx.x;
    const int lane = tid & 31, wid = tid >> 5;
    const int brow = blockIdx.x * 128;

    // ---- load A rows (fp32), split bf16 hi/lo into smem ----
    {
        const int row = tid & 127;
        const int kh = tid >> 7;     // 0 or 1: which 64-col half
        const int grow = brow + row;
        const bool ok = grow < NN;
        const float* ar = A + (size_t)grow * 128 + kh * 64;
        __nv_bfloat16* dh = sAhi + row * LDA + kh * 64;
        __nv_bfloat16* dl = sAlo + row * LDA + kh * 64;
#pragma unroll
        for (int c = 0; c < 8; c++) {
            float f[8];
            if (ok) {
                float4 v0 = *reinterpret_cast<const float4*>(ar + c * 8);
                float4 v1 = *reinterpret_cast<const float4*>(ar + c * 8 + 4);
                f[0] = v0.x; f[1] = v0.y; f[2] = v0.z; f[3] = v0.w;
                f[4] = v1.x; f[5] = v1.y; f[6] = v1.z; f[7] = v1.w;
            } else {
#pragma unroll
                for (int p = 0; p < 8; p++) f[p] = 0.f;
            }
            uint32_t hp[4], lp[4];
#pragma unroll
            for (int p = 0; p < 4; p++) {
                __nv_bfloat16 h0 = __float2bfloat16(f[2 * p]);
                __nv_bfloat16 h1 = __float2bfloat16(f[2 * p + 1]);
                __nv_bfloat16 l0 = __float2bfloat16(f[2 * p] - __bfloat162float(h0));
                __nv_bfloat16 l1 = __float2bfloat16(f[2 * p + 1] - __bfloat162float(h1));
                hp[p] = pack2(h0, h1);
                lp[p] = pack2(l0, l1);
            }
            *reinterpret_cast<uint4*>(dh + c * 8) = make_uint4(hp[0], hp[1], hp[2], hp[3]);
            *reinterpret_cast<uint4*>(dl + c * 8) = make_uint4(lp[0], lp[1], lp[2], lp[3]);
        }
    }
    // ---- copy prepacked B tile into smem (padded rows) ----
    {
        const uint4* bh = reinterpret_cast<const uint4*>(g_Bhi + (size_t)btile * 16384);
        const uint4* bl = reinterpret_cast<const uint4*>(g_Blo + (size_t)btile * 16384);
#pragma unroll
        for (int it = 0; it < 8; it++) {
            int j = tid + it * 256;            // 2048 uint4 total
            int row = j >> 4, kc = (j & 15) * 8;
            *reinterpret_cast<uint4*>(sBhi + row * LDA + kc) = bh[j];
            *reinterpret_cast<uint4*>(sBlo + row * LDA + kc) = bl[j];
        }
    }
    __syncthreads();

    // ---- warp tiling: 4x2 warps, each 32 rows x 64 cols ----
    const int wr = wid & 3;   // 0..3
    const int wc = wid >> 1 & 0;  // placeholder (computed below properly)
    const int wcol = wid >> 2; // 0..1

    // per-lane ldmatrix element offsets
    const int aRow = wr * 32 + (lane & 15);
    const int aK   = (lane >> 4) * 8;
    const int gg   = lane >> 3;
    const int bRow = wcol * 64 + (gg >> 1) * 8 + (lane & 7);
    const int bK   = (gg & 1) * 8;

    const int aOff = aRow * LDA + aK;   // elems
    const int bOff = bRow * LDA + bK;

    float acc[2][8][4];
#pragma unroll
    for (int i = 0; i < 2; i++)
#pragma unroll
        for (int j = 0; j < 8; j++)
#pragma unroll
            for (int q = 0; q < 4; q++) acc[i][j][q] = 0.f;

#pragma unroll
    for (int t = 0; t < 3; t++) {
        const __nv_bfloat16* Ab = (t == 2) ? sAlo : sAhi;
        const __nv_bfloat16* Bb = (t == 1) ? sBlo : sBhi;
        const uint32_t aBase = smem_u32(Ab + aOff);
        const uint32_t bBase = smem_u32(Bb + bOff);
#pragma unroll
        for (int kb = 0; kb < 8; kb++) {
            uint32_t a[2][4];
            ldsm4(a[0], aBase + kb * 32);
            ldsm4(a[1], aBase + 16 * LDA * 2 + kb * 32);
            uint32_t b[4][4];
#pragma unroll
            for (int p = 0; p < 4; p++)
                ldsm4(b[p], bBase + p * 16 * LDA * 2 + kb * 32);
#pragma unroll
            for (int i = 0; i < 2; i++)
#pragma unroll
                for (int j = 0; j < 8; j++)
                    mma16816(acc[i][j], a[i], b[j >> 1][(j & 1) * 2], b[j >> 1][(j & 1) * 2 + 1]);
        }
    }

    // ---- epilogue: write fp32 frags to global (+bias for sel 0) ----
    const int colb = blockIdx.y * 128 + wcol * 64;
#pragma unroll
    for (int i = 0; i < 2; i++) {
        int row0 = brow + wr * 32 + i * 16 + (lane >> 2);
        int row1 = row0 + 8;
#pragma unroll
        for (int j = 0; j < 8; j++) {
            int col = colb + j * 8 + (lane & 3) * 2;
            float bx = 0.f, by = 0.f;
            if (usebias) { bx = g_bias[col]; by = g_bias[col + 1]; }
            if (row0 < NN) {
                float2 v = make_float2(acc[i][j][0] + bx, acc[i][j][1] + by);
                *reinterpret_cast<float2*>(out + (size_t)row0 * ostride + col) = v;
            }
            if (row1 < NN) {
                float2 v = make_float2(acc[i][j][2] + bx, acc[i][j][3] + by);
                *reinterpret_cast<float2*>(out + (size_t)row1 * ostride + col) = v;
            }
        }
    }
}

// ---------------- edge pass: one warp per edge, pure gather/scatter ----------------
__global__ void k_edge(const float* __restrict__ h_child, const float* __restrict__ c_child,
                       const int* __restrict__ esrc, const int* __restrict__ edst) {
    int idx = blockIdx.x * blockDim.x + threadIdx.x;
    int e = idx >> 5;
    int q = idx & 31;
    if (e >= NE) return;
    int s = esrc[e];
    int d = edst[e];
    float4 h4  = reinterpret_cast<const float4*>(h_child + (size_t)s * HS)[q];
    float4 hu4 = reinterpret_cast<const float4*>(g_hu + (size_t)s * HS)[q];
    float4 c4  = reinterpret_cast<const float4*>(c_child + (size_t)s * HS)[q];
    float4 xf4 = reinterpret_cast<const float4*>(g_xall + (size_t)d * 512 + 384)[q];
    float* hs = g_hsum + (size_t)d * HS + q * 4;
    float* fc = g_fcsum + (size_t)d * HS + q * 4;
    atomicAdd(hs + 0, h4.x); atomicAdd(hs + 1, h4.y);
    atomicAdd(hs + 2, h4.z); atomicAdd(hs + 3, h4.w);
    atomicAdd(fc + 0, sigmoidf(xf4.x + hu4.x) * c4.x);
    atomicAdd(fc + 1, sigmoidf(xf4.y + hu4.y) * c4.y);
    atomicAdd(fc + 2, sigmoidf(xf4.z + hu4.z) * c4.z);
    atomicAdd(fc + 3, sigmoidf(xf4.w + hu4.w) * c4.w);
}

// ---------------- final node update ----------------
__global__ void k_final(float* __restrict__ out) {
    int idx = blockIdx.x * blockDim.x + threadIdx.x;
    if (idx >= NN * HS) return;
    int n = idx >> 7;
    int j = idx & 127;
    size_t bx = (size_t)n * 512;
    size_t bu = (size_t)n * 384;
    float i_ = sigmoidf(g_xall[bx + j]       + g_uhsum[bu + j]);
    float o_ = sigmoidf(g_xall[bx + 128 + j] + g_uhsum[bu + 128 + j]);
    float u_ = tanhf(   g_xall[bx + 256 + j] + g_uhsum[bu + 256 + j]);
    float c = i_ * u_ + g_fcsum[idx];
    float h = o_ * tanhf(c);
    out[idx] = h;
    out[(size_t)NN * HS + idx] = c;
}

// ============================================================================
extern "C" void kernel_launch(void* const* d_in, const int* in_sizes, int n_in,
                              void* d_out, int out_size) {
    const float* x       = (const float*)d_in[0];
    const float* h_child = (const float*)d_in[1];
    const float* c_child = (const float*)d_in[2];
    const float* w_iou   = (const float*)d_in[3];
    const float* b_iou   = (const float*)d_in[4];
    const float* w_f     = (const float*)d_in[5];
    const float* b_f     = (const float*)d_in[6];
    const float* u_iou   = (const float*)d_in[7];
    const float* u_f     = (const float*)d_in[8];
    const int*   esrc    = (const int*)d_in[9];
    const int*   edst    = (const int*)d_in[10];
    float* out = (float*)d_out;

    static bool configured = false;
    if (!configured) {
        cudaFuncSetAttribute(k_mma, cudaFuncAttributeMaxDynamicSharedMemorySize, SMEM_BYTES);
        configured = true;
    }

    k_zero<<<(NN * HS / 4 + 255) / 256, 256>>>();
    k_prep<<<131072 / 256, 256>>>(w_iou, w_f, u_iou, u_f, b_iou, b_f);
    k_mma<<<dim3(ROW_TILES, 4), 256, SMEM_BYTES>>>(x, h_child, 0);  // x -> g_xall
    k_mma<<<dim3(ROW_TILES, 1), 256, SMEM_BYTES>>>(x, h_child, 1);  // h_child -> g_hu
    k_edge<<<(NE * 32) / 256, 256>>>(h_child, c_child, esrc, edst);
    k_mma<<<dim3(ROW_TILES, 3), 256, SMEM_BYTES>>>(x, h_child, 2);  // g_hsum -> g_uhsum
    k_final<<<(NN * HS + 255) / 256, 256>>>(out);
}

// round 6
// speedup vs baseline: 1.6172x; 1.1122x over previous
#include <cuda_runtime.h>
#include <cuda_bf16.h>
#include <cstdint>

#define NN 200000
#define NE 400000
#define HS 128
#define ROW_TILES 1563            // ceil(200000/128)
#define NPAD (ROW_TILES * 128)    // 200064 padded rows

#define LDA 136                   // padded smem row stride (elems)
#define ASZ (128 * LDA)           // elems per smem tile buffer
// smem: A hi/lo + B 2 stages x (hi/lo)  = 6 tile buffers
#define SMEM_BYTES (6 * ASZ * 2)

// ---------------- scratch (device globals; no allocs allowed) ----------------
// NOTE: never passed as kernel args from host (host shadow + ATS trap);
// all resolution happens inside device code via `sel`.
__device__ float g_xall[(size_t)NN * 512];   // x@[w_iou;w_f]^T + bias  [N,512] = i|o|u|xf
__device__ float g_hu[(size_t)NN * HS];      // h_child @ u_f^T         [N,128]
__device__ float g_hsum[(size_t)NN * HS];    // segsum(h_child[src])    [N,128]
__device__ float g_fcsum[(size_t)NN * HS];   // segsum(f*c_child[src])  [N,128]
__device__ float g_uhsum[(size_t)NN * 384];  // hsum @ u_iou^T          [N,384]
// pre-split bf16 A operands (padded; tail rows stay zero from module-load init)
__device__ __align__(16) __nv_bfloat16 g_xhi[(size_t)NPAD * HS];
__device__ __align__(16) __nv_bfloat16 g_xlo[(size_t)NPAD * HS];
__device__ __align__(16) __nv_bfloat16 g_hhi[(size_t)NPAD * HS];
__device__ __align__(16) __nv_bfloat16 g_hlo[(size_t)NPAD * HS];
__device__ __align__(16) __nv_bfloat16 g_shi[(size_t)NPAD * HS];
__device__ __align__(16) __nv_bfloat16 g_slo[(size_t)NPAD * HS];
// packed bf16 weights, 8 tiles of [128 n][128 k] row-major:
// tiles 0-3: [w_iou;w_f] (512 rows), 4-6: u_iou (384), 7: u_f (128)
__device__ __align__(16) __nv_bfloat16 g_Bhi[8 * 16384];
__device__ __align__(16) __nv_bfloat16 g_Blo[8 * 16384];
__device__ __align__(16) float g_bias[512];

__device__ __forceinline__ float sigmoidf(float v) { return 1.0f / (1.0f + __expf(-v)); }

__device__ __forceinline__ uint32_t smem_u32(const void* p) {
    uint32_t a;
    asm("{ .reg .u64 t; cvta.to.shared.u64 t, %1; cvt.u32.u64 %0, t; }" : "=r"(a) : "l"(p));
    return a;
}

__device__ __forceinline__ void ldsm4(uint32_t* r, uint32_t addr) {
    asm volatile("ldmatrix.sync.aligned.m8n8.x4.shared.b16 {%0,%1,%2,%3}, [%4];"
                 : "=r"(r[0]), "=r"(r[1]), "=r"(r[2]), "=r"(r[3]) : "r"(addr));
}

__device__ __forceinline__ void mma16816(float* c, const uint32_t* a, uint32_t b0, uint32_t b1) {
    asm volatile(
        "mma.sync.aligned.m16n8k16.row.col.f32.bf16.bf16.f32 "
        "{%0,%1,%2,%3}, {%4,%5,%6,%7}, {%8,%9}, {%0,%1,%2,%3};"
        : "+f"(c[0]), "+f"(c[1]), "+f"(c[2]), "+f"(c[3])
        : "r"(a[0]), "r"(a[1]), "r"(a[2]), "r"(a[3]), "r"(b0), "r"(b1));
}

__device__ __forceinline__ void cp16(uint32_t dst, const void* src) {
    asm volatile("cp.async.cg.shared.global [%0], [%1], 16;" :: "r"(dst), "l"(src));
}
__device__ __forceinline__ void cp_commit() {
    asm volatile("cp.async.commit_group;");
}
template <int N>
__device__ __forceinline__ void cp_wait() {
    asm volatile("cp.async.wait_group %0;" :: "n"(N));
}

__device__ __forceinline__ uint32_t pack2(__nv_bfloat16 lo, __nv_bfloat16 hi) {
    return (uint32_t)__bfloat16_as_ushort(lo) | ((uint32_t)__bfloat16_as_ushort(hi) << 16);
}

// ---------------- zero the accumulators ----------------
__global__ void k_zero() {
    int i = blockIdx.x * blockDim.x + threadIdx.x;
    const int total4 = NN * HS / 4;
    if (i < total4) {
        float4 z = make_float4(0.f, 0.f, 0.f, 0.f);
        reinterpret_cast<float4*>(g_hsum)[i] = z;
        reinterpret_cast<float4*>(g_fcsum)[i] = z;
    }
}

// ---------------- split fp32 -> bf16 hi/lo (4 elems per thread) ----------------
// sel 0: src=ext (x)       -> g_xhi/g_xlo
// sel 1: src=ext (h_child) -> g_hhi/g_hlo
// sel 2: src=g_hsum        -> g_shi/g_slo
__global__ void k_split(const float* __restrict__ ext, int sel) {
    const int total4 = NN * HS / 4;
    int i = blockIdx.x * blockDim.x + threadIdx.x;
    if (i >= total4) return;
    const float* src = (sel == 2) ? g_hsum : ext;
    __nv_bfloat16* hi = (sel == 0) ? g_xhi : (sel == 1) ? g_hhi : g_shi;
    __nv_bfloat16* lo = (sel == 0) ? g_xlo : (sel == 1) ? g_hlo : g_slo;
    float4 v = reinterpret_cast<const float4*>(src)[i];
    float f[4] = {v.x, v.y, v.z, v.w};
    uint32_t hp[2], lp[2];
#pragma unroll
    for (int p = 0; p < 2; p++) {
        __nv_bfloat16 h0 = __float2bfloat16(f[2 * p]);
        __nv_bfloat16 h1 = __float2bfloat16(f[2 * p + 1]);
        __nv_bfloat16 l0 = __float2bfloat16(f[2 * p] - __bfloat162float(h0));
        __nv_bfloat16 l1 = __float2bfloat16(f[2 * p + 1] - __bfloat162float(h1));
        hp[p] = pack2(h0, h1);
        lp[p] = pack2(l0, l1);
    }
    reinterpret_cast<uint2*>(hi)[i] = make_uint2(hp[0], hp[1]);
    reinterpret_cast<uint2*>(lo)[i] = make_uint2(lp[0], lp[1]);
}

// ---------------- pack weights: fp32 -> bf16 hi/lo, row-major [n][k] tiles ----------------
__global__ void k_prep(const float* __restrict__ w_iou, const float* __restrict__ w_f,
                       const float* __restrict__ u_iou, const float* __restrict__ u_f,
                       const float* __restrict__ b_iou, const float* __restrict__ b_f) {
    int i = blockIdx.x * blockDim.x + threadIdx.x;
    if (i < 512) g_bias[i] = (i < 384) ? b_iou[i] : b_f[i - 384];
    if (i >= 131072) return;
    int n, k, tile;
    float val;
    if (i < 65536) {                       // [w_iou ; w_f], 512 rows
        n = i >> 7; k = i & 127;
        tile = n >> 7;
        val = (n < 384) ? w_iou[n * 128 + k] : w_f[(n - 384) * 128 + k];
    } else if (i < 65536 + 49152) {        // u_iou, 384 rows
        int j = i - 65536;
        n = j >> 7; k = j & 127;
        tile = 4 + (n >> 7);
        val = u_iou[n * 128 + k];
    } else {                               // u_f, 128 rows
        int j = i - 114688;
        n = j >> 7; k = j & 127;
        tile = 7;
        val = u_f[n * 128 + k];
    }
    __nv_bfloat16 hi = __float2bfloat16(val);
    __nv_bfloat16 lo = __float2bfloat16(val - __bfloat162float(hi));
    int off = tile * 16384 + (n & 127) * 128 + k;
    g_Bhi[off] = hi;
    g_Blo[off] = lo;
}

// copy one [128][128] bf16 tile, global row-major -> smem padded LDA, via cp.async
__device__ __forceinline__ void copy_tile(uint32_t sdst, const __nv_bfloat16* gsrc, int tid) {
#pragma unroll
    for (int it = 0; it < 8; it++) {
        int j = tid + it * 256;        // 2048 16B chunks
        int r = j >> 4, c = j & 15;
        cp16(sdst + (uint32_t)(r * LDA + c * 8) * 2, gsrc + r * 128 + c * 8);
    }
}

// ============================================================================
// bf16 mma.sync GEMM with column-tile loop + double-buffered B.
// sel 0: A=g_xhi/lo -> g_xall  (stride 512, +bias, btiles 0..3)
// sel 1: A=g_hhi/lo -> g_hu    (stride 128, btile 7)
// sel 2: A=g_shi/lo -> g_uhsum (stride 384, btiles 4..6)
// 3-term split: Ahi*Bhi + Ahi*Blo + Alo*Bhi.
// ============================================================================
__global__ void __launch_bounds__(256) k_mma(int sel) {
    const __nv_bfloat16* Ahi = (sel == 0) ? g_xhi : (sel == 1) ? g_hhi : g_shi;
    const __nv_bfloat16* Alo = (sel == 0) ? g_xlo : (sel == 1) ? g_hlo : g_slo;
    float* out = (sel == 0) ? g_xall : (sel == 1) ? g_hu : g_uhsum;
    const int ostride = (sel == 0) ? 512 : (sel == 1) ? 128 : 384;
    const int first   = (sel == 0) ? 0 : (sel == 1) ? 7 : 4;
    const int ntiles  = (sel == 0) ? 4 : (sel == 1) ? 1 : 3;
    const int usebias = (sel == 0);

    extern __shared__ __nv_bfloat16 sm[];

    const int tid = threadIdx.x;
    const int lane = tid & 31, wid = tid >> 5;
    const int brow = blockIdx.x * 128;

    const uint32_t sA32 = smem_u32(sm);
    const uint32_t sB32 = sA32 + 2 * ASZ * 2;

    // prologue: A hi/lo + B tile 0 (stage 0)
    copy_tile(sA32, Ahi + (size_t)brow * 128, tid);
    copy_tile(sA32 + ASZ * 2, Alo + (size_t)brow * 128, tid);
    copy_tile(sB32, g_Bhi + (size_t)first * 16384, tid);
    copy_tile(sB32 + ASZ * 2, g_Blo + (size_t)first * 16384, tid);
    cp_commit();

    // ---- warp tiling: 4x2 warps, each 32 rows x 64 cols ----
    const int wr = wid & 3;
    const int wcol = wid >> 2;
    const int aRow = wr * 32 + (lane & 15);
    const int aK   = (lane >> 4) * 8;
    const int gg   = lane >> 3;
    const int bRow = wcol * 64 + (gg >> 1) * 8 + (lane & 7);
    const int bK   = (gg & 1) * 8;
    const uint32_t aHiB = sA32 + (uint32_t)(aRow * LDA + aK) * 2;
    const uint32_t aLoB = aHiB + ASZ * 2;
    const uint32_t bOffB = (uint32_t)(bRow * LDA + bK) * 2;

    for (int t = 0; t < ntiles; t++) {
        // prefetch next B tile into other stage
        if (t + 1 < ntiles) {
            uint32_t st = ((t + 1) & 1) ? (sB32 + 2 * ASZ * 2) : sB32;
            copy_tile(st, g_Bhi + (size_t)(first + t + 1) * 16384, tid);
            copy_tile(st + ASZ * 2, g_Blo + (size_t)(first + t + 1) * 16384, tid);
            cp_commit();
            cp_wait<1>();
        } else {
            cp_wait<0>();
        }
        __syncthreads();

        const uint32_t stage = (t & 1) ? (sB32 + 2 * ASZ * 2) : sB32;
        const uint32_t bHiB = stage + bOffB;
        const uint32_t bLoB = bHiB + ASZ * 2;

        float acc[2][8][4];
#pragma unroll
        for (int i = 0; i < 2; i++)
#pragma unroll
            for (int j = 0; j < 8; j++)
#pragma unroll
                for (int q = 0; q < 4; q++) acc[i][j][q] = 0.f;

#pragma unroll
        for (int t3 = 0; t3 < 3; t3++) {
            const uint32_t aBase = (t3 == 2) ? aLoB : aHiB;
            const uint32_t bBase = (t3 == 1) ? bLoB : bHiB;
#pragma unroll
            for (int kb = 0; kb < 8; kb++) {
                uint32_t a[2][4];
                ldsm4(a[0], aBase + kb * 32);
                ldsm4(a[1], aBase + 16 * LDA * 2 + kb * 32);
                uint32_t b[4][4];
#pragma unroll
                for (int p = 0; p < 4; p++)
                    ldsm4(b[p], bBase + p * 16 * LDA * 2 + kb * 32);
#pragma unroll
                for (int i = 0; i < 2; i++)
#pragma unroll
                    for (int j = 0; j < 8; j++)
                        mma16816(acc[i][j], a[i], b[j >> 1][(j & 1) * 2], b[j >> 1][(j & 1) * 2 + 1]);
            }
        }

        // ---- epilogue for this column tile ----
        const int colb = t * 128 + wcol * 64;
#pragma unroll
        for (int i = 0; i < 2; i++) {
            int row0 = brow + wr * 32 + i * 16 + (lane >> 2);
            int row1 = row0 + 8;
#pragma unroll
            for (int j = 0; j < 8; j++) {
                int col = colb + j * 8 + (lane & 3) * 2;
                float bx = 0.f, by = 0.f;
                if (usebias) { bx = g_bias[col]; by = g_bias[col + 1]; }
                if (row0 < NN) {
                    float2 v = make_float2(acc[i][j][0] + bx, acc[i][j][1] + by);
                    *reinterpret_cast<float2*>(out + (size_t)row0 * ostride + col) = v;
                }
                if (row1 < NN) {
                    float2 v = make_float2(acc[i][j][2] + bx, acc[i][j][3] + by);
                    *reinterpret_cast<float2*>(out + (size_t)row1 * ostride + col) = v;
                }
            }
        }
        __syncthreads();
    }
}

// ---------------- edge pass: one warp per edge, pure gather/scatter ----------------
__global__ void k_edge(const float* __restrict__ h_child, const float* __restrict__ c_child,
                       const int* __restrict__ esrc, const int* __restrict__ edst) {
    int idx = blockIdx.x * blockDim.x + threadIdx.x;
    int e = idx >> 5;
    int q = idx & 31;
    if (e >= NE) return;
    int s = esrc[e];
    int d = edst[e];
    float4 h4  = reinterpret_cast<const float4*>(h_child + (size_t)s * HS)[q];
    float4 hu4 = reinterpret_cast<const float4*>(g_hu + (size_t)s * HS)[q];
    float4 c4  = reinterpret_cast<const float4*>(c_child + (size_t)s * HS)[q];
    float4 xf4 = reinterpret_cast<const float4*>(g_xall + (size_t)d * 512 + 384)[q];
    float* hs = g_hsum + (size_t)d * HS + q * 4;
    float* fc = g_fcsum + (size_t)d * HS + q * 4;
    atomicAdd(hs + 0, h4.x); atomicAdd(hs + 1, h4.y);
    atomicAdd(hs + 2, h4.z); atomicAdd(hs + 3, h4.w);
    atomicAdd(fc + 0, sigmoidf(xf4.x + hu4.x) * c4.x);
    atomicAdd(fc + 1, sigmoidf(xf4.y + hu4.y) * c4.y);
    atomicAdd(fc + 2, sigmoidf(xf4.z + hu4.z) * c4.z);
    atomicAdd(fc + 3, sigmoidf(xf4.w + hu4.w) * c4.w);
}

// ---------------- final node update ----------------
__global__ void k_final(float* __restrict__ out) {
    int idx = blockIdx.x * blockDim.x + threadIdx.x;
    if (idx >= NN * HS) return;
    int n = idx >> 7;
    int j = idx & 127;
    size_t bx = (size_t)n * 512;
    size_t bu = (size_t)n * 384;
    float i_ = sigmoidf(g_xall[bx + j]       + g_uhsum[bu + j]);
    float o_ = sigmoidf(g_xall[bx + 128 + j] + g_uhsum[bu + 128 + j]);
    float u_ = tanhf(   g_xall[bx + 256 + j] + g_uhsum[bu + 256 + j]);
    float c = i_ * u_ + g_fcsum[idx];
    float h = o_ * tanhf(c);
    out[idx] = h;
    out[(size_t)NN * HS + idx] = c;
}

// ============================================================================
extern "C" void kernel_launch(void* const* d_in, const int* in_sizes, int n_in,
                              void* d_out, int out_size) {
    const float* x       = (const float*)d_in[0];
    const float* h_child = (const float*)d_in[1];
    const float* c_child = (const float*)d_in[2];
    const float* w_iou   = (const float*)d_in[3];
    const float* b_iou   = (const float*)d_in[4];
    const float* w_f     = (const float*)d_in[5];
    const float* b_f     = (const float*)d_in[6];
    const float* u_iou   = (const float*)d_in[7];
    const float* u_f     = (const float*)d_in[8];
    const int*   esrc    = (const int*)d_in[9];
    const int*   edst    = (const int*)d_in[10];
    float* out = (float*)d_out;

    static bool configured = false;
    if (!configured) {
        cudaFuncSetAttribute(k_mma, cudaFuncAttributeMaxDynamicSharedMemorySize, SMEM_BYTES);
        configured = true;
    }

    const int total4 = NN * HS / 4;
    const int sgrid = (total4 + 255) / 256;

    k_zero<<<(total4 + 255) / 256, 256>>>();
    k_prep<<<131072 / 256, 256>>>(w_iou, w_f, u_iou, u_f, b_iou, b_f);
    k_split<<<sgrid, 256>>>(x, 0);
    k_split<<<sgrid, 256>>>(h_child, 1);
    k_mma<<<ROW_TILES, 256, SMEM_BYTES>>>(0);   // x -> g_xall
    k_mma<<<ROW_TILES, 256, SMEM_BYTES>>>(1);   // h_child -> g_hu
    k_edge<<<(NE * 32) / 256, 256>>>(h_child, c_child, esrc, edst);
    k_split<<<sgrid, 256>>>(nullptr, 2);
    k_mma<<<ROW_TILES, 256, SMEM_BYTES>>>(2);   // g_hsum -> g_uhsum
    k_final<<<(NN * HS + 255) / 256, 256>>>(out);
}